// round 1
// baseline (speedup 1.0000x reference)
#include <cuda_runtime.h>
#include <cstdint>

#define N_ANCH   300000
#define N_CLS    80
#define DET_DIM  85
#define TOPK     1000
#define MAXBOX   300
#define CAP      4096
#define NMS_THR  0.4f

// ---------------- device scratch (no allocations allowed) ----------------
__device__ unsigned int       g_scores[N_ANCH];
__device__ unsigned int       g_hist[256];
__device__ unsigned int       g_prefix;
__device__ int                g_kth;
__device__ int                g_cand_cnt;
__device__ unsigned long long g_cand[CAP];
__device__ int                g_topk_idx[TOPK];
__device__ float4             g_boxk[TOPK];
__device__ unsigned int       g_maskmat[TOPK * 32];

// ---------------- 1. per-anchor max over 80 classes + state init ----------------
__global__ void score_kernel(const float* __restrict__ cls) {
    if (blockIdx.x == 0) {
        if (threadIdx.x < 256) g_hist[threadIdx.x] = 0u;
        if (threadIdx.x == 0) { g_prefix = 0u; g_kth = TOPK; g_cand_cnt = 0; }
    }
    int a = blockIdx.x * blockDim.x + threadIdx.x;
    if (a >= N_ANCH) return;
    const float4* row = (const float4*)(cls + (size_t)a * N_CLS);
    float m = -1e30f;
#pragma unroll
    for (int j = 0; j < N_CLS / 4; j++) {
        float4 v = row[j];
        m = fmaxf(m, fmaxf(fmaxf(v.x, v.y), fmaxf(v.z, v.w)));
    }
    // scores are >= 0 -> float bits are monotonic as unsigned
    g_scores[a] = __float_as_uint(m);
}

// ---------------- 2. radix-select (4 rounds of 8 bits, descending) ----------------
__global__ void hist_kernel(int shift) {
    __shared__ unsigned int sh[256];
    if (threadIdx.x < 256) sh[threadIdx.x] = 0u;
    __syncthreads();
    unsigned int prefix = g_prefix;
    unsigned int mask = (shift >= 24) ? 0u : (0xFFFFFFFFu << (shift + 8));
    for (int i = blockIdx.x * blockDim.x + threadIdx.x; i < N_ANCH;
         i += gridDim.x * blockDim.x) {
        unsigned int k = g_scores[i];
        if (((k ^ prefix) & mask) == 0u)
            atomicAdd(&sh[(k >> shift) & 255u], 1u);
    }
    __syncthreads();
    if (threadIdx.x < 256 && sh[threadIdx.x])
        atomicAdd(&g_hist[threadIdx.x], sh[threadIdx.x]);
}

__global__ void resolve_kernel(int shift) {
    __shared__ unsigned int h[256];
    int t = threadIdx.x;
    h[t] = g_hist[t];
    __syncthreads();
    if (t == 0) {
        int kth = g_kth;
        unsigned int cum = 0;
        for (int b = 255; b >= 0; b--) {
            unsigned int c = h[b];
            if (cum + c >= (unsigned int)kth) {
                g_kth = kth - (int)cum;
                g_prefix |= ((unsigned int)b) << shift;
                break;
            }
            cum += c;
        }
    }
    __syncthreads();
    g_hist[t] = 0u;  // ready for next round / next replay
}

// ---------------- 3. compact candidates (key >= T) ----------------
__global__ void compact_kernel() {
    int i = blockIdx.x * blockDim.x + threadIdx.x;
    if (i >= N_ANCH) return;
    unsigned int T = g_prefix;  // full 32-bit threshold after round 4
    unsigned int k = g_scores[i];
    if (k >= T) {
        int slot = atomicAdd(&g_cand_cnt, 1);
        if (slot < CAP)
            g_cand[slot] = ((unsigned long long)k << 32) |
                           (unsigned long long)(0xFFFFFFFFu - (unsigned int)i);
    }
}

// ---------------- 4. bitonic sort descending -> exact stable top-k, gather boxes ----------------
__global__ void sort_kernel(const float* __restrict__ boxes) {
    __shared__ unsigned long long s[CAP];
    int tid = threadIdx.x;
    int cnt = g_cand_cnt;
    if (cnt > CAP) cnt = CAP;
    for (int i = tid; i < CAP; i += blockDim.x)
        s[i] = (i < cnt) ? g_cand[i] : 0ull;
    __syncthreads();
    for (int k = 2; k <= CAP; k <<= 1) {
        for (int j = k >> 1; j > 0; j >>= 1) {
            for (int idx = tid; idx < CAP; idx += blockDim.x) {
                int l = idx ^ j;
                if (l > idx) {
                    bool up = ((idx & k) == 0);
                    unsigned long long a = s[idx], b = s[l];
                    bool sw = up ? (a < b) : (a > b);  // descending network
                    if (sw) { s[idx] = b; s[l] = a; }
                }
            }
            __syncthreads();
        }
    }
    if (tid < TOPK) {
        unsigned long long key = s[tid];
        int idx = (int)(0xFFFFFFFFu - (unsigned int)key);
        g_topk_idx[tid] = idx;
        g_boxk[tid] = ((const float4*)boxes)[idx];  // (y1,x1,y2,x2)
    }
}

// ---------------- 5. IoU > thr bitmask matrix (bit-exact vs reference fp32) ----------------
__global__ void mask_kernel() {
    int w = blockIdx.x * blockDim.x + threadIdx.x;
    if (w >= TOPK * 32) return;
    int i = w >> 5, wj = w & 31;
    float4 bi = g_boxk[i];
    float ai = __fmul_rn(__fsub_rn(bi.z, bi.x), __fsub_rn(bi.w, bi.y));
    unsigned int bits = 0u;
    int j0 = wj * 32;
#pragma unroll 8
    for (int t = 0; t < 32; t++) {
        int j = j0 + t;
        if (j < TOPK) {
            float4 bj = g_boxk[j];
            float aj = __fmul_rn(__fsub_rn(bj.z, bj.x), __fsub_rn(bj.w, bj.y));
            float ih = fmaxf(__fsub_rn(fminf(bi.z, bj.z), fmaxf(bi.x, bj.x)), 0.0f);
            float iw = fmaxf(__fsub_rn(fminf(bi.w, bj.w), fmaxf(bi.y, bj.y)), 0.0f);
            float inter = __fmul_rn(ih, iw);
            float denom = __fadd_rn(__fsub_rn(__fadd_rn(ai, aj), inter), 1e-8f);
            float iou = __fdiv_rn(inter, denom);
            if (iou > NMS_THR) bits |= (1u << t);
        }
    }
    g_maskmat[w] = bits;
}

// ---------------- 6. sequential greedy keep-scan + output gather ----------------
__global__ void scan_out_kernel(const float* __restrict__ det, float* __restrict__ out) {
    extern __shared__ unsigned int smask[];  // TOPK*32 words
    __shared__ unsigned int keepw[32];
    __shared__ unsigned int wpref[32];
    __shared__ int s_sel[MAXBOX];
    __shared__ int s_nkeep;
    int tid = threadIdx.x;
    for (int i = tid; i < TOPK * 32; i += blockDim.x) smask[i] = g_maskmat[i];
    __syncthreads();

    if (tid < 32) {  // warp 0: the serial scan
        unsigned int kw = 0u;
        for (int i = 0; i < TOPK; i++) {
            unsigned int m = smask[i * 32 + tid];
            int any = __any_sync(0xFFFFFFFFu, (kw & m) != 0u);
            if (!any && tid == (i >> 5)) kw |= 1u << (i & 31);
        }
        keepw[tid] = kw;
        unsigned int pc = __popc(kw);
        unsigned int inc = pc;
        for (int off = 1; off < 32; off <<= 1) {
            unsigned int v = __shfl_up_sync(0xFFFFFFFFu, inc, off);
            if (tid >= off) inc += v;
        }
        wpref[tid] = inc - pc;           // exclusive prefix of keep counts
        if (tid == 31) s_nkeep = (int)inc;
    }
    __syncthreads();

    if (tid < TOPK) {
        int w = tid >> 5, b = tid & 31;
        unsigned int kw = keepw[w];
        if ((kw >> b) & 1u) {
            int rank = (int)wpref[w] + __popc(kw & ((1u << b) - 1u));
            if (rank < MAXBOX) s_sel[rank] = g_topk_idx[tid];
        }
    }
    __syncthreads();

    int nk = s_nkeep;
    if (nk > MAXBOX) nk = MAXBOX;
    for (int e = tid; e < MAXBOX * DET_DIM; e += blockDim.x) {
        int r = e / DET_DIM;
        int c = e - r * DET_DIM;
        out[e] = (r < nk) ? det[(size_t)s_sel[r] * DET_DIM + c] : 0.0f;
    }
}

// ---------------- launch ----------------
extern "C" void kernel_launch(void* const* d_in, const int* in_sizes, int n_in,
                              void* d_out, int out_size) {
    const float* boxes = (const float*)d_in[0];
    const float* cls   = (const float*)d_in[1];
    const float* det   = (const float*)d_in[2];
    float* out = (float*)d_out;

    cudaFuncSetAttribute(scan_out_kernel,
                         cudaFuncAttributeMaxDynamicSharedMemorySize,
                         TOPK * 32 * sizeof(unsigned int));

    score_kernel<<<(N_ANCH + 255) / 256, 256>>>(cls);
    for (int s = 24; s >= 0; s -= 8) {
        hist_kernel<<<256, 256>>>(s);
        resolve_kernel<<<1, 256>>>(s);
    }
    compact_kernel<<<(N_ANCH + 255) / 256, 256>>>();
    sort_kernel<<<1, 1024>>>(boxes);
    mask_kernel<<<(TOPK * 32 + 255) / 256, 256>>>();
    scan_out_kernel<<<1, 1024, TOPK * 32 * sizeof(unsigned int)>>>(det, out);
}